// round 11
// baseline (speedup 1.0000x reference)
#include <cuda_runtime.h>
#include <cstdint>

#define MAXN 100000
#define MAXE 1000000
#define HDIM 64
#define AGG_CTAS 512   // capped agg grid: leaves SM headroom for co-resident GEMMs

// ---------------------------------------------------------------------------
// Static device scratch (no allocation allowed)
// ---------------------------------------------------------------------------
__device__ float g_A1 [2 * MAXN * HDIM];   // layer1 pre-act (h1 = relu(A1); residual)
__device__ float g_AE1[2 * MAXN * HDIM];   // layer2 pre-act (e1 = relu(AE1))
__device__ float g_B  [2 * MAXN * HDIM];   // layer3 pre-act
__device__ float g_C  [2 * MAXN * HDIM];   // layer4 pre-act
__device__ float g_HW [4 * MAXN * HDIM];   // 4 GEMM outputs (single set — L2 residency)
__device__ int   g_cnt   [4 * MAXN];
__device__ int   g_rowptr[4 * (MAXN + 1)];
__device__ int   g_rowofs[4 * MAXN];
__device__ int2  g_cv    [4 * MAXE];
__device__ int   g_part  [4 * 512];

// ---------------------------------------------------------------------------
// Packed fp32x2 FMA helpers (PTX fma.rn.f32x2 -> FFMA2; exact fp32)
// ---------------------------------------------------------------------------
__device__ __forceinline__ unsigned long long pack2(float x) {
    unsigned long long r;
    asm("mov.b64 %0, {%1, %1};" : "=l"(r) : "f"(x));
    return r;
}
__device__ __forceinline__ void ffma2(unsigned long long& d, unsigned long long a,
                                      unsigned long long b) {
    asm("fma.rn.f32x2 %0, %1, %2, %3;" : "=l"(d) : "l"(a), "l"(b), "l"(d));
}
__device__ __forceinline__ void unpack2(unsigned long long v, float& lo, float& hi) {
    asm("mov.b64 {%0, %1}, %2;" : "=f"(lo), "=f"(hi) : "l"(v));
}

// ---------------------------------------------------------------------------
// SIMT GEMM (FFMA2): out[N,64] = act(h)[N,DIN] @ W[DIN,64]
// 256 threads, tile 128 rows x 64 cols, 8x4 register tile (as 8x2 f32x2).
// ---------------------------------------------------------------------------
template <int DIN, bool RELU>
__global__ __launch_bounds__(256) void gemm_kernel(
    float* __restrict__ out, const float* __restrict__ h,
    const float* __restrict__ W, int N) {
    extern __shared__ float smem[];
    float* Ws = smem;              // [DIN][64]
    float* hs = smem + DIN * 64;   // [128][DIN]

    const int tid  = threadIdx.x;
    const int row0 = blockIdx.x * 128;

    for (int i = tid; i < DIN * 16; i += 256)
        reinterpret_cast<float4*>(Ws)[i] = reinterpret_cast<const float4*>(W)[i];

    const int VPR = DIN / 4;
    for (int i = tid; i < 128 * VPR; i += 256) {
        int r = i / VPR, kc = i % VPR;
        int gr = row0 + r;
        float4 v = make_float4(0.f, 0.f, 0.f, 0.f);
        if (gr < N) v = reinterpret_cast<const float4*>(h)[(size_t)gr * VPR + kc];
        if (RELU) {
            v.x = fmaxf(v.x, 0.f); v.y = fmaxf(v.y, 0.f);
            v.z = fmaxf(v.z, 0.f); v.w = fmaxf(v.w, 0.f);
        }
        reinterpret_cast<float4*>(hs)[r * VPR + kc] = v;
    }
    __syncthreads();

    const int tx = tid & 15;   // col group: cols 4*tx..4*tx+3
    const int ty = tid >> 4;   // row group: rows 8*ty..8*ty+7

    unsigned long long acc[8][2];
#pragma unroll
    for (int i = 0; i < 8; i++) { acc[i][0] = 0ull; acc[i][1] = 0ull; }

#pragma unroll 4
    for (int k = 0; k < DIN; k += 4) {
        unsigned long long b2[4][2];
#pragma unroll
        for (int kk = 0; kk < 4; kk++) {
            double2 bd = *reinterpret_cast<double2*>(&Ws[(k + kk) * 64 + tx * 4]);
            b2[kk][0] = __double_as_longlong(bd.x);
            b2[kk][1] = __double_as_longlong(bd.y);
        }
#pragma unroll
        for (int i = 0; i < 8; i++) {
            float4 a = *reinterpret_cast<float4*>(&hs[(ty * 8 + i) * DIN + k]);
            const float* av = reinterpret_cast<const float*>(&a);
#pragma unroll
            for (int kk = 0; kk < 4; kk++) {
                unsigned long long aa = pack2(av[kk]);
                ffma2(acc[i][0], aa, b2[kk][0]);
                ffma2(acc[i][1], aa, b2[kk][1]);
            }
        }
    }

#pragma unroll
    for (int i = 0; i < 8; i++) {
        int r = row0 + ty * 8 + i;
        if (r < N) {
            float4 v;
            unpack2(acc[i][0], v.x, v.y);
            unpack2(acc[i][1], v.z, v.w);
            reinterpret_cast<float4*>(out + (size_t)r * 64 + tx * 4)[0] = v;
        }
    }
}

// ---------------------------------------------------------------------------
// CSR build kernels
// ---------------------------------------------------------------------------
__global__ void hist_kernel(int* __restrict__ cnt, const int* __restrict__ rows,
                            int E, int N) {
    int i = blockIdx.x * blockDim.x + threadIdx.x;
    if (i >= 4 * E) return;
    int t = i / E;
    atomicAdd(&cnt[t * N + __ldg(rows + i)], 1);
}

__global__ void scan_phase1(const int* __restrict__ cnt, int* __restrict__ part,
                            int N, int nb) {
    int t = blockIdx.y, b = blockIdx.x;
    int i = b * 256 + threadIdx.x;
    int v = (i < N) ? cnt[t * N + i] : 0;
#pragma unroll
    for (int o = 16; o; o >>= 1) v += __shfl_down_sync(0xffffffffu, v, o);
    __shared__ int ws[8];
    if ((threadIdx.x & 31) == 0) ws[threadIdx.x >> 5] = v;
    __syncthreads();
    if (threadIdx.x == 0) {
        int s = 0;
#pragma unroll
        for (int j = 0; j < 8; j++) s += ws[j];
        part[t * nb + b] = s;
    }
}

__global__ void scan_phase2(int* __restrict__ part, int* __restrict__ rowptr,
                            int nb, int N, int E) {
    int t = threadIdx.x;
    if (t >= 4) return;
    int s = 0;
    for (int b = 0; b < nb; b++) {
        int v = part[t * nb + b];
        part[t * nb + b] = s;
        s += v;
    }
    rowptr[t * (N + 1) + N] = E;
}

__global__ void scan_phase3(const int* __restrict__ cnt, const int* __restrict__ part,
                            int* __restrict__ rowptr, int* __restrict__ rowofs,
                            int N, int nb) {
    int t = blockIdx.y, b = blockIdx.x;
    int i = b * 256 + threadIdx.x;
    int v = (i < N) ? cnt[t * N + i] : 0;
    __shared__ int sm[256];
    sm[threadIdx.x] = v;
    __syncthreads();
#pragma unroll
    for (int o = 1; o < 256; o <<= 1) {
        int x = (threadIdx.x >= o) ? sm[threadIdx.x - o] : 0;
        __syncthreads();
        sm[threadIdx.x] += x;
        __syncthreads();
    }
    if (i < N) {
        int excl = sm[threadIdx.x] - v + part[t * nb + b];
        rowptr[t * (N + 1) + i] = excl;
        rowofs[t * N + i] = excl;
    }
}

__global__ void fill_kernel(int2* __restrict__ cv, int* __restrict__ rowofs,
                            const int* __restrict__ rows, const int* __restrict__ cols,
                            const float* __restrict__ vals, int E, int N) {
    int i = blockIdx.x * blockDim.x + threadIdx.x;
    if (i >= 4 * E) return;
    int t = i / E;
    int r = __ldg(rows + i);
    int pos = atomicAdd(&rowofs[t * N + r], 1);
    cv[(size_t)t * E + pos] = make_int2(__ldg(cols + i), __float_as_int(__ldg(vals + i)));
}

// ---------------------------------------------------------------------------
// CSR aggregation, 4-deep gather unroll, grid-stride with capped grid
// ---------------------------------------------------------------------------
__device__ __forceinline__ void fma4(float4& acc, float v, const float4& x) {
    acc.x = fmaf(v, x.x, acc.x);
    acc.y = fmaf(v, x.y, acc.y);
    acc.z = fmaf(v, x.z, acc.z);
    acc.w = fmaf(v, x.w, acc.w);
}

__device__ __forceinline__ void agg_one(float4& acc0, float4& acc1,
                                        const float4* __restrict__ hw,
                                        const int* __restrict__ rp,
                                        const int2* __restrict__ cv, int r, int c) {
    int b = __ldg(rp + r);
    int e = __ldg(rp + r + 1);
    for (; b + 4 <= e; b += 4) {
        int2 p0 = __ldg(cv + b);
        int2 p1 = __ldg(cv + b + 1);
        int2 p2 = __ldg(cv + b + 2);
        int2 p3 = __ldg(cv + b + 3);
        float4 x0 = __ldg(hw + (size_t)p0.x * 16 + c);
        float4 x1 = __ldg(hw + (size_t)p1.x * 16 + c);
        float4 x2 = __ldg(hw + (size_t)p2.x * 16 + c);
        float4 x3 = __ldg(hw + (size_t)p3.x * 16 + c);
        fma4(acc0, __int_as_float(p0.y), x0);
        fma4(acc1, __int_as_float(p1.y), x1);
        fma4(acc0, __int_as_float(p2.y), x2);
        fma4(acc1, __int_as_float(p3.y), x3);
    }
    for (; b < e; b++) {
        int2 p = __ldg(cv + b);
        float4 x = __ldg(hw + (size_t)p.x * 16 + c);
        fma4(acc0, __int_as_float(p.y), x);
    }
}

__global__ __launch_bounds__(256) void agg2_kernel(
    float4* __restrict__ out,
    const float4* __restrict__ hw0, const float4* __restrict__ hw1,
    const int* __restrict__ rp0, const int2* __restrict__ cv0,
    const int* __restrict__ rp1, const int2* __restrict__ cv1, int N) {
    const int stride = gridDim.x * blockDim.x;
    for (int gid = blockIdx.x * blockDim.x + threadIdx.x; gid < N * 16; gid += stride) {
        int r = gid >> 4, c = gid & 15;
        float4 a0 = make_float4(0.f, 0.f, 0.f, 0.f);
        float4 a1 = make_float4(0.f, 0.f, 0.f, 0.f);
        agg_one(a0, a1, hw0, rp0, cv0, r, c);
        agg_one(a0, a1, hw1, rp1, cv1, r, c);
        out[(size_t)r * 16 + c] = make_float4(a0.x + a1.x, a0.y + a1.y,
                                              a0.z + a1.z, a0.w + a1.w);
    }
}

// Layer-5 agg fused with the final attention-concat epilogue (one node class).
__global__ __launch_bounds__(256) void agg2_final_kernel(
    float* __restrict__ out,
    const float4* __restrict__ A1, const float4* __restrict__ AE1,
    const float4* __restrict__ hw0, const float4* __restrict__ hw1,
    const int* __restrict__ rp0, const int2* __restrict__ cv0,
    const int* __restrict__ rp1, const int2* __restrict__ cv1,
    const float* __restrict__ att, int N) {
    const int stride = gridDim.x * blockDim.x;
    float a0 = __ldg(att + 0), a1 = __ldg(att + 1), a2 = __ldg(att + 2);
    for (int gid = blockIdx.x * blockDim.x + threadIdx.x; gid < N * 16; gid += stride) {
        int r = gid >> 4, c = gid & 15;

        float4 a0v = make_float4(0.f, 0.f, 0.f, 0.f);
        float4 a1v = make_float4(0.f, 0.f, 0.f, 0.f);
        agg_one(a0v, a1v, hw0, rp0, cv0, r, c);
        agg_one(a0v, a1v, hw1, rp1, cv1, r, c);
        float4 p = make_float4(a0v.x + a1v.x, a0v.y + a1v.y, a0v.z + a1v.z, a0v.w + a1v.w);

        float4 x1 = A1[(size_t)r * 16 + c];
        x1.x = fmaxf(x1.x, 0.f); x1.y = fmaxf(x1.y, 0.f);
        x1.z = fmaxf(x1.z, 0.f); x1.w = fmaxf(x1.w, 0.f);

        float4 xe = AE1[(size_t)r * 16 + c];
        xe.x = fmaxf(xe.x, 0.f); xe.y = fmaxf(xe.y, 0.f);
        xe.z = fmaxf(xe.z, 0.f); xe.w = fmaxf(xe.w, 0.f);

        float4 emb = make_float4(p.x + x1.x, p.y + x1.y, p.z + x1.z, p.w + x1.w);

        float* o = out + (size_t)r * 192 + (size_t)c * 4;
        reinterpret_cast<float4*>(o + 0)[0]   = make_float4(x1.x * a0, x1.y * a0, x1.z * a0, x1.w * a0);
        reinterpret_cast<float4*>(o + 64)[0]  = make_float4(xe.x * a1, xe.y * a1, xe.z * a1, xe.w * a1);
        reinterpret_cast<float4*>(o + 128)[0] = make_float4(emb.x * a2, emb.y * a2, emb.z * a2, emb.w * a2);
    }
}

// ---------------------------------------------------------------------------
// Host launcher — R7 symmetric fork (S0: t0,t1,A01; S1: t3,t2,A23),
// CSR on SC, capped agg grids enabling real co-residency.
// ---------------------------------------------------------------------------
struct PipeCtx {
    cudaStream_t s1, sc;
    cudaEvent_t efork, eCSR;
    cudaEvent_t e0[5];  // S0's A01 done (per layer)
    cudaEvent_t e1[5];  // S1's A23 done (per layer)
    PipeCtx() {
        cudaStreamCreateWithFlags(&s1, cudaStreamNonBlocking);
        cudaStreamCreateWithFlags(&sc, cudaStreamNonBlocking);
        cudaEventCreateWithFlags(&efork, cudaEventDisableTiming);
        cudaEventCreateWithFlags(&eCSR,  cudaEventDisableTiming);
        for (int i = 0; i < 5; i++) {
            cudaEventCreateWithFlags(&e0[i], cudaEventDisableTiming);
            cudaEventCreateWithFlags(&e1[i], cudaEventDisableTiming);
        }
    }
};
static PipeCtx& pipe_ctx() { static PipeCtx c; return c; }

extern "C" void kernel_launch(void* const* d_in, const int* in_sizes, int n_in,
                              void* d_out, int out_size) {
    const float* feat0 = (const float*)d_in[0];
    const float* feat1 = (const float*)d_in[1];
    const int*   rows  = (const int*)  d_in[2];
    const int*   cols  = (const int*)  d_in[3];
    const float* vals  = (const float*)d_in[4];
    const float* Wl[5] = {(const float*)d_in[5], (const float*)d_in[6], (const float*)d_in[7],
                          (const float*)d_in[8], (const float*)d_in[9]};
    const float* att   = (const float*)d_in[10];
    float* out = (float*)d_out;

    const int N = in_sizes[0] / 128;   // 100000
    const int E = in_sizes[2] / 4;     // 1000000

    float *A1, *AE1, *B, *C, *HW;
    int *cnt, *rowptr, *rowofs, *part;
    int2* cv;
    cudaGetSymbolAddress((void**)&A1,     g_A1);
    cudaGetSymbolAddress((void**)&AE1,    g_AE1);
    cudaGetSymbolAddress((void**)&B,      g_B);
    cudaGetSymbolAddress((void**)&C,      g_C);
    cudaGetSymbolAddress((void**)&HW,     g_HW);
    cudaGetSymbolAddress((void**)&cnt,    g_cnt);
    cudaGetSymbolAddress((void**)&rowptr, g_rowptr);
    cudaGetSymbolAddress((void**)&rowofs, g_rowofs);
    cudaGetSymbolAddress((void**)&cv,     g_cv);
    cudaGetSymbolAddress((void**)&part,   g_part);

    const int SMEM64  = (64 * 64 + 128 * 64) * 4;    // 48 KB
    const int SMEM128 = (128 * 64 + 128 * 128) * 4;  // 96 KB
    cudaFuncSetAttribute(gemm_kernel<128, false>, cudaFuncAttributeMaxDynamicSharedMemorySize, SMEM128);
    cudaFuncSetAttribute(gemm_kernel<64, true>,   cudaFuncAttributeMaxDynamicSharedMemorySize, SMEM64);

    PipeCtx& px = pipe_ctx();
    cudaStream_t S0 = 0, S1 = px.s1, SC = px.sc;

    const int gblocks = (N + 127) / 128;
    const size_t half = (size_t)N * 64;

    auto rp  = [&](int t) { return rowptr + (size_t)t * (N + 1); };
    auto cvp = [&](int t) { return cv + (size_t)t * E; };
    auto hw  = [&](int t) { return HW + (size_t)t * half; };

    // ---- fork ----
    cudaEventRecord(px.efork, S0);
    cudaStreamWaitEvent(S1, px.efork, 0);
    cudaStreamWaitEvent(SC, px.efork, 0);

    // ---- CSR build on SC (overlaps layer-0 GEMMs on S0/S1) ----
    const int nb = (N + 255) / 256;
    cudaMemsetAsync(cnt, 0, (size_t)4 * N * sizeof(int), SC);
    {
        int blocks = (4 * E + 255) / 256;
        hist_kernel<<<blocks, 256, 0, SC>>>(cnt, rows, E, N);
        scan_phase1<<<dim3(nb, 4), 256, 0, SC>>>(cnt, part, N, nb);
        scan_phase2<<<1, 32, 0, SC>>>(part, rowptr, nb, N, E);
        scan_phase3<<<dim3(nb, 4), 256, 0, SC>>>(cnt, part, rowptr, rowofs, N, nb);
        fill_kernel<<<blocks, 256, 0, SC>>>(cv, rowofs, rows, cols, vals, E, N);
    }
    cudaEventRecord(px.eCSR, SC);

    auto gemm = [&](cudaStream_t s, int l, int t, const float* src, int din) {
        const float* Wt = Wl[l] + (size_t)t * din * 64;
        if (din == 128)
            gemm_kernel<128, false><<<gblocks, 256, SMEM128, s>>>(hw(t), src, Wt, N);
        else
            gemm_kernel<64, true><<<gblocks, 256, SMEM64, s>>>(hw(t), src, Wt, N);
    };

    float* dsts[4] = {A1, AE1, B, C};
    for (int l = 0; l < 5; l++) {
        const float* p0;
        const float* p1;
        int din = (l == 0) ? 128 : 64;
        if (l == 0) { p0 = feat0; p1 = feat1; }
        else        { p0 = dsts[l - 1]; p1 = dsts[l - 1] + half; }

        // ----- S0 chain: G0(p0), [p1 ready] G1(p1), A01 -----
        gemm(S0, l, 0, p0, din);
        if (l > 0) cudaStreamWaitEvent(S0, px.e1[l - 1], 0);
        gemm(S0, l, 1, p1, din);
        if (l == 0) cudaStreamWaitEvent(S0, px.eCSR, 0);
        // ----- S1 chain: G3(p1), [p0 ready] G2(p0), A23 -----
        gemm(S1, l, 3, p1, din);
        if (l > 0) cudaStreamWaitEvent(S1, px.e0[l - 1], 0);
        gemm(S1, l, 2, p0, din);
        if (l == 0) cudaStreamWaitEvent(S1, px.eCSR, 0);

        if (l < 4) {
            float* dst = dsts[l];
            agg2_kernel<<<AGG_CTAS, 256, 0, S0>>>((float4*)dst,
                (const float4*)hw(0), (const float4*)hw(1), rp(0), cvp(0), rp(1), cvp(1), N);
            cudaEventRecord(px.e0[l], S0);
            agg2_kernel<<<AGG_CTAS, 256, 0, S1>>>((float4*)(dst + half),
                (const float4*)hw(2), (const float4*)hw(3), rp(2), cvp(2), rp(3), cvp(3), N);
            cudaEventRecord(px.e1[l], S1);
        } else {
            agg2_final_kernel<<<AGG_CTAS, 256, 0, S0>>>(out,
                (const float4*)A1, (const float4*)AE1,
                (const float4*)hw(0), (const float4*)hw(1),
                rp(0), cvp(0), rp(1), cvp(1), att, N);
            cudaEventRecord(px.e0[l], S0);
            agg2_final_kernel<<<AGG_CTAS, 256, 0, S1>>>(out + (size_t)N * 192,
                (const float4*)(A1 + half), (const float4*)(AE1 + half),
                (const float4*)hw(2), (const float4*)hw(3),
                rp(2), cvp(2), rp(3), cvp(3), att, N);
            cudaEventRecord(px.e1[l], S1);
        }
    }

    // ---- join back to capture-origin stream ----
    cudaStreamWaitEvent(S0, px.e1[4], 0);
}

// round 12
// speedup vs baseline: 1.5108x; 1.5108x over previous
#include <cuda_runtime.h>
#include <cuda_fp16.h>
#include <cstdint>

#define MAXN 100000
#define MAXE 1000000
#define HDIM 64

// ---------------------------------------------------------------------------
// Static device scratch (no allocation allowed)
// ---------------------------------------------------------------------------
__device__ float  g_A1 [2 * MAXN * HDIM];   // layer1 pre-act (fp32)
__device__ float  g_AE1[2 * MAXN * HDIM];   // layer2 pre-act (fp32)
__device__ float  g_B  [2 * MAXN * HDIM];   // layer3 pre-act (fp32)
__device__ float  g_C  [2 * MAXN * HDIM];   // layer4 pre-act (fp32)
__device__ __half g_HW [4 * MAXN * HDIM];   // GEMM outputs in fp16 (gather-only data)
__device__ int    g_cnt   [4 * MAXN];
__device__ int    g_rowptr[4 * (MAXN + 1)];
__device__ int    g_rowofs[4 * MAXN];
__device__ int2   g_cv    [4 * MAXE];
__device__ int    g_part  [4 * 512];

// ---------------------------------------------------------------------------
// Packed fp32x2 FMA helpers (PTX fma.rn.f32x2 -> FFMA2; exact fp32)
// ---------------------------------------------------------------------------
__device__ __forceinline__ unsigned long long pack2(float x) {
    unsigned long long r;
    asm("mov.b64 %0, {%1, %1};" : "=l"(r) : "f"(x));
    return r;
}
__device__ __forceinline__ void ffma2(unsigned long long& d, unsigned long long a,
                                      unsigned long long b) {
    asm("fma.rn.f32x2 %0, %1, %2, %3;" : "=l"(d) : "l"(a), "l"(b), "l"(d));
}
__device__ __forceinline__ void unpack2(unsigned long long v, float& lo, float& hi) {
    asm("mov.b64 {%0, %1}, %2;" : "=f"(lo), "=f"(hi) : "l"(v));
}

// ---------------------------------------------------------------------------
// SIMT GEMM (FFMA2): hw[N,64](fp16) = act(h)[N,DIN](fp32) @ W[DIN,64](fp32)
// 256 threads, tile 128 rows x 64 cols, 8x4 register tile (as 8x2 f32x2).
// ---------------------------------------------------------------------------
template <int DIN, bool RELU>
__global__ __launch_bounds__(256) void gemm_kernel(
    __half* __restrict__ out, const float* __restrict__ h,
    const float* __restrict__ W, int N) {
    extern __shared__ float smem[];
    float* Ws = smem;              // [DIN][64]
    float* hs = smem + DIN * 64;   // [128][DIN]

    const int tid  = threadIdx.x;
    const int row0 = blockIdx.x * 128;

    for (int i = tid; i < DIN * 16; i += 256)
        reinterpret_cast<float4*>(Ws)[i] = reinterpret_cast<const float4*>(W)[i];

    const int VPR = DIN / 4;
    for (int i = tid; i < 128 * VPR; i += 256) {
        int r = i / VPR, kc = i % VPR;
        int gr = row0 + r;
        float4 v = make_float4(0.f, 0.f, 0.f, 0.f);
        if (gr < N) v = reinterpret_cast<const float4*>(h)[(size_t)gr * VPR + kc];
        if (RELU) {
            v.x = fmaxf(v.x, 0.f); v.y = fmaxf(v.y, 0.f);
            v.z = fmaxf(v.z, 0.f); v.w = fmaxf(v.w, 0.f);
        }
        reinterpret_cast<float4*>(hs)[r * VPR + kc] = v;
    }
    __syncthreads();

    const int tx = tid & 15;   // col group: cols 4*tx..4*tx+3
    const int ty = tid >> 4;   // row group: rows 8*ty..8*ty+7

    unsigned long long acc[8][2];
#pragma unroll
    for (int i = 0; i < 8; i++) { acc[i][0] = 0ull; acc[i][1] = 0ull; }

#pragma unroll 4
    for (int k = 0; k < DIN; k += 4) {
        unsigned long long b2[4][2];
#pragma unroll
        for (int kk = 0; kk < 4; kk++) {
            double2 bd = *reinterpret_cast<double2*>(&Ws[(k + kk) * 64 + tx * 4]);
            b2[kk][0] = __double_as_longlong(bd.x);
            b2[kk][1] = __double_as_longlong(bd.y);
        }
#pragma unroll
        for (int i = 0; i < 8; i++) {
            float4 a = *reinterpret_cast<float4*>(&hs[(ty * 8 + i) * DIN + k]);
            const float* av = reinterpret_cast<const float*>(&a);
#pragma unroll
            for (int kk = 0; kk < 4; kk++) {
                unsigned long long aa = pack2(av[kk]);
                ffma2(acc[i][0], aa, b2[kk][0]);
                ffma2(acc[i][1], aa, b2[kk][1]);
            }
        }
    }

#pragma unroll
    for (int i = 0; i < 8; i++) {
        int r = row0 + ty * 8 + i;
        if (r < N) {
            float4 v;
            unpack2(acc[i][0], v.x, v.y);
            unpack2(acc[i][1], v.z, v.w);
            __half2 h01 = __floats2half2_rn(v.x, v.y);
            __half2 h23 = __floats2half2_rn(v.z, v.w);
            // 4 halves = 8B, 8-byte aligned (tx*4 halves)
            uint2 st = make_uint2(*reinterpret_cast<uint32_t*>(&h01),
                                  *reinterpret_cast<uint32_t*>(&h23));
            *reinterpret_cast<uint2*>(out + (size_t)r * 64 + tx * 4) = st;
        }
    }
}

// ---------------------------------------------------------------------------
// CSR build kernels
// ---------------------------------------------------------------------------
__global__ void hist_kernel(int* __restrict__ cnt, const int* __restrict__ rows,
                            int E, int N) {
    int i = blockIdx.x * blockDim.x + threadIdx.x;
    if (i >= 4 * E) return;
    int t = i / E;
    atomicAdd(&cnt[t * N + __ldg(rows + i)], 1);
}

__global__ void scan_phase1(const int* __restrict__ cnt, int* __restrict__ part,
                            int N, int nb) {
    int t = blockIdx.y, b = blockIdx.x;
    int i = b * 256 + threadIdx.x;
    int v = (i < N) ? cnt[t * N + i] : 0;
#pragma unroll
    for (int o = 16; o; o >>= 1) v += __shfl_down_sync(0xffffffffu, v, o);
    __shared__ int ws[8];
    if ((threadIdx.x & 31) == 0) ws[threadIdx.x >> 5] = v;
    __syncthreads();
    if (threadIdx.x == 0) {
        int s = 0;
#pragma unroll
        for (int j = 0; j < 8; j++) s += ws[j];
        part[t * nb + b] = s;
    }
}

__global__ void scan_phase2(int* __restrict__ part, int* __restrict__ rowptr,
                            int nb, int N, int E) {
    int t = threadIdx.x;
    if (t >= 4) return;
    int s = 0;
    for (int b = 0; b < nb; b++) {
        int v = part[t * nb + b];
        part[t * nb + b] = s;
        s += v;
    }
    rowptr[t * (N + 1) + N] = E;
}

__global__ void scan_phase3(const int* __restrict__ cnt, const int* __restrict__ part,
                            int* __restrict__ rowptr, int* __restrict__ rowofs,
                            int N, int nb) {
    int t = blockIdx.y, b = blockIdx.x;
    int i = b * 256 + threadIdx.x;
    int v = (i < N) ? cnt[t * N + i] : 0;
    __shared__ int sm[256];
    sm[threadIdx.x] = v;
    __syncthreads();
#pragma unroll
    for (int o = 1; o < 256; o <<= 1) {
        int x = (threadIdx.x >= o) ? sm[threadIdx.x - o] : 0;
        __syncthreads();
        sm[threadIdx.x] += x;
        __syncthreads();
    }
    if (i < N) {
        int excl = sm[threadIdx.x] - v + part[t * nb + b];
        rowptr[t * (N + 1) + i] = excl;
        rowofs[t * N + i] = excl;
    }
}

__global__ void fill_kernel(int2* __restrict__ cv, int* __restrict__ rowofs,
                            const int* __restrict__ rows, const int* __restrict__ cols,
                            const float* __restrict__ vals, int E, int N) {
    int i = blockIdx.x * blockDim.x + threadIdx.x;
    if (i >= 4 * E) return;
    int t = i / E;
    int r = __ldg(rows + i);
    int pos = atomicAdd(&rowofs[t * N + r], 1);
    cv[(size_t)t * E + pos] = make_int2(__ldg(cols + i), __float_as_int(__ldg(vals + i)));
}

// ---------------------------------------------------------------------------
// CSR aggregation over fp16 hw: 8 lanes per row, each lane owns 8 halves (16B).
// Accumulation in fp32. 4-edge unroll, 2 independent accumulator chains.
// ---------------------------------------------------------------------------
__device__ __forceinline__ void fma8(float acc[8], float v, uint4 x) {
    const __half2* h = reinterpret_cast<const __half2*>(&x);
#pragma unroll
    for (int i = 0; i < 4; i++) {
        float2 f = __half22float2(h[i]);
        acc[2 * i]     = fmaf(v, f.x, acc[2 * i]);
        acc[2 * i + 1] = fmaf(v, f.y, acc[2 * i + 1]);
    }
}

__device__ __forceinline__ void agg_one(float acc0[8], float acc1[8],
                                        const uint4* __restrict__ hw,
                                        const int* __restrict__ rp,
                                        const int2* __restrict__ cv, int r, int c) {
    int b = __ldg(rp + r);
    int e = __ldg(rp + r + 1);
    for (; b + 4 <= e; b += 4) {
        int2 p0 = __ldg(cv + b);
        int2 p1 = __ldg(cv + b + 1);
        int2 p2 = __ldg(cv + b + 2);
        int2 p3 = __ldg(cv + b + 3);
        uint4 x0 = __ldg(hw + (size_t)p0.x * 8 + c);
        uint4 x1 = __ldg(hw + (size_t)p1.x * 8 + c);
        uint4 x2 = __ldg(hw + (size_t)p2.x * 8 + c);
        uint4 x3 = __ldg(hw + (size_t)p3.x * 8 + c);
        fma8(acc0, __int_as_float(p0.y), x0);
        fma8(acc1, __int_as_float(p1.y), x1);
        fma8(acc0, __int_as_float(p2.y), x2);
        fma8(acc1, __int_as_float(p3.y), x3);
    }
    for (; b < e; b++) {
        int2 p = __ldg(cv + b);
        uint4 x = __ldg(hw + (size_t)p.x * 8 + c);
        fma8(acc0, __int_as_float(p.y), x);
    }
}

__global__ __launch_bounds__(256) void agg2_kernel(
    float4* __restrict__ out,
    const uint4* __restrict__ hw0, const uint4* __restrict__ hw1,
    const int* __restrict__ rp0, const int2* __restrict__ cv0,
    const int* __restrict__ rp1, const int2* __restrict__ cv1, int N) {
    int gid = blockIdx.x * blockDim.x + threadIdx.x;
    if (gid >= N * 8) return;
    int r = gid >> 3, c = gid & 7;
    float acc0[8], acc1[8];
#pragma unroll
    for (int i = 0; i < 8; i++) { acc0[i] = 0.f; acc1[i] = 0.f; }
    agg_one(acc0, acc1, hw0, rp0, cv0, r, c);
    agg_one(acc0, acc1, hw1, rp1, cv1, r, c);
    float4 v0 = make_float4(acc0[0] + acc1[0], acc0[1] + acc1[1],
                            acc0[2] + acc1[2], acc0[3] + acc1[3]);
    float4 v1 = make_float4(acc0[4] + acc1[4], acc0[5] + acc1[5],
                            acc0[6] + acc1[6], acc0[7] + acc1[7]);
    out[(size_t)r * 16 + c * 2]     = v0;
    out[(size_t)r * 16 + c * 2 + 1] = v1;
}

// Layer-5 agg fused with the final attention-concat epilogue (one node class).
// out row r: [0:64) relu(A1)*a0 | [64:128) relu(AE1)*a1 | [128:192) (p+relu(A1))*a2
__global__ __launch_bounds__(256) void agg2_final_kernel(
    float* __restrict__ out,
    const float4* __restrict__ A1, const float4* __restrict__ AE1,
    const uint4* __restrict__ hw0, const uint4* __restrict__ hw1,
    const int* __restrict__ rp0, const int2* __restrict__ cv0,
    const int* __restrict__ rp1, const int2* __restrict__ cv1,
    const float* __restrict__ att, int N) {
    int gid = blockIdx.x * blockDim.x + threadIdx.x;
    if (gid >= N * 8) return;
    int r = gid >> 3, c = gid & 7;

    float acc0[8], acc1[8];
#pragma unroll
    for (int i = 0; i < 8; i++) { acc0[i] = 0.f; acc1[i] = 0.f; }
    agg_one(acc0, acc1, hw0, rp0, cv0, r, c);
    agg_one(acc0, acc1, hw1, rp1, cv1, r, c);

    float a0 = __ldg(att + 0), a1 = __ldg(att + 1), a2 = __ldg(att + 2);

    float4 x1a = A1[(size_t)r * 16 + c * 2];
    float4 x1b = A1[(size_t)r * 16 + c * 2 + 1];
    x1a.x = fmaxf(x1a.x, 0.f); x1a.y = fmaxf(x1a.y, 0.f);
    x1a.z = fmaxf(x1a.z, 0.f); x1a.w = fmaxf(x1a.w, 0.f);
    x1b.x = fmaxf(x1b.x, 0.f); x1b.y = fmaxf(x1b.y, 0.f);
    x1b.z = fmaxf(x1b.z, 0.f); x1b.w = fmaxf(x1b.w, 0.f);

    float4 xea = AE1[(size_t)r * 16 + c * 2];
    float4 xeb = AE1[(size_t)r * 16 + c * 2 + 1];
    xea.x = fmaxf(xea.x, 0.f); xea.y = fmaxf(xea.y, 0.f);
    xea.z = fmaxf(xea.z, 0.f); xea.w = fmaxf(xea.w, 0.f);
    xeb.x = fmaxf(xeb.x, 0.f); xeb.y = fmaxf(xeb.y, 0.f);
    xeb.z = fmaxf(xeb.z, 0.f); xeb.w = fmaxf(xeb.w, 0.f);

    float* o = out + (size_t)r * 192 + (size_t)c * 8;
    reinterpret_cast<float4*>(o)[0] =
        make_float4(x1a.x * a0, x1a.y * a0, x1a.z * a0, x1a.w * a0);
    reinterpret_cast<float4*>(o + 4)[0] =
        make_float4(x1b.x * a0, x1b.y * a0, x1b.z * a0, x1b.w * a0);
    reinterpret_cast<float4*>(o + 64)[0] =
        make_float4(xea.x * a1, xea.y * a1, xea.z * a1, xea.w * a1);
    reinterpret_cast<float4*>(o + 68)[0] =
        make_float4(xeb.x * a1, xeb.y * a1, xeb.z * a1, xeb.w * a1);
    reinterpret_cast<float4*>(o + 128)[0] =
        make_float4((acc0[0] + acc1[0] + x1a.x) * a2, (acc0[1] + acc1[1] + x1a.y) * a2,
                    (acc0[2] + acc1[2] + x1a.z) * a2, (acc0[3] + acc1[3] + x1a.w) * a2);
    reinterpret_cast<float4*>(o + 132)[0] =
        make_float4((acc0[4] + acc1[4] + x1b.x) * a2, (acc0[5] + acc1[5] + x1b.y) * a2,
                    (acc0[6] + acc1[6] + x1b.z) * a2, (acc0[7] + acc1[7] + x1b.w) * a2);
}

// ---------------------------------------------------------------------------
// Host launcher — R10 schedule: R7 symmetric fork + CSR on SC + fused final.
// ---------------------------------------------------------------------------
struct PipeCtx {
    cudaStream_t s1, sc;
    cudaEvent_t efork, eCSR;
    cudaEvent_t e0[5];  // S0's A01 done (per layer)
    cudaEvent_t e1[5];  // S1's A23 done (per layer)
    PipeCtx() {
        cudaStreamCreateWithFlags(&s1, cudaStreamNonBlocking);
        cudaStreamCreateWithFlags(&sc, cudaStreamNonBlocking);
        cudaEventCreateWithFlags(&efork, cudaEventDisableTiming);
        cudaEventCreateWithFlags(&eCSR,  cudaEventDisableTiming);
        for (int i = 0; i < 5; i++) {
            cudaEventCreateWithFlags(&e0[i], cudaEventDisableTiming);
            cudaEventCreateWithFlags(&e1[i], cudaEventDisableTiming);
        }
    }
};
static PipeCtx& pipe_ctx() { static PipeCtx c; return c; }

extern "C" void kernel_launch(void* const* d_in, const int* in_sizes, int n_in,
                              void* d_out, int out_size) {
    const float* feat0 = (const float*)d_in[0];
    const float* feat1 = (const float*)d_in[1];
    const int*   rows  = (const int*)  d_in[2];
    const int*   cols  = (const int*)  d_in[3];
    const float* vals  = (const float*)d_in[4];
    const float* Wl[5] = {(const float*)d_in[5], (const float*)d_in[6], (const float*)d_in[7],
                          (const float*)d_in[8], (const float*)d_in[9]};
    const float* att   = (const float*)d_in[10];
    float* out = (float*)d_out;

    const int N = in_sizes[0] / 128;   // 100000
    const int E = in_sizes[2] / 4;     // 1000000

    float *A1, *AE1, *B, *C;
    __half* HW;
    int *cnt, *rowptr, *rowofs, *part;
    int2* cv;
    cudaGetSymbolAddress((void**)&A1,     g_A1);
    cudaGetSymbolAddress((void**)&AE1,    g_AE1);
    cudaGetSymbolAddress((void**)&B,      g_B);
    cudaGetSymbolAddress((void**)&C,      g_C);
    cudaGetSymbolAddress((void**)&HW,     g_HW);
    cudaGetSymbolAddress((void**)&cnt,    g_cnt);
    cudaGetSymbolAddress((void**)&rowptr, g_rowptr);
    cudaGetSymbolAddress((void**)&rowofs, g_rowofs);
    cudaGetSymbolAddress((void**)&cv,     g_cv);
    cudaGetSymbolAddress((void**)&part,   g_part);

    const int SMEM64  = (64 * 64 + 128 * 64) * 4;    // 48 KB
    const int SMEM128 = (128 * 64 + 128 * 128) * 4;  // 96 KB
    cudaFuncSetAttribute(gemm_kernel<128, false>, cudaFuncAttributeMaxDynamicSharedMemorySize, SMEM128);
    cudaFuncSetAttribute(gemm_kernel<64, true>,   cudaFuncAttributeMaxDynamicSharedMemorySize, SMEM64);

    PipeCtx& px = pipe_ctx();
    cudaStream_t S0 = 0, S1 = px.s1, SC = px.sc;

    const int gblocks = (N + 127) / 128;
    const int ablocks = (N * 8 + 255) / 256;
    const size_t half = (size_t)N * 64;

    auto rp  = [&](int t) { return rowptr + (size_t)t * (N + 1); };
    auto cvp = [&](int t) { return cv + (size_t)t * E; };
    auto hw  = [&](int t) { return HW + (size_t)t * half; };

    // ---- fork ----
    cudaEventRecord(px.efork, S0);
    cudaStreamWaitEvent(S1, px.efork, 0);
    cudaStreamWaitEvent(SC, px.efork, 0);

    // ---- CSR build on SC (overlaps layer-0 GEMMs on S0/S1) ----
    const int nb = (N + 255) / 256;
    cudaMemsetAsync(cnt, 0, (size_t)4 * N * sizeof(int), SC);
    {
        int blocks = (4 * E + 255) / 256;
        hist_kernel<<<blocks, 256, 0, SC>>>(cnt, rows, E, N);
        scan_phase1<<<dim3(nb, 4), 256, 0, SC>>>(cnt, part, N, nb);
        scan_phase2<<<1, 32, 0, SC>>>(part, rowptr, nb, N, E);
        scan_phase3<<<dim3(nb, 4), 256, 0, SC>>>(cnt, part, rowptr, rowofs, N, nb);
        fill_kernel<<<blocks, 256, 0, SC>>>(cv, rowofs, rows, cols, vals, E, N);
    }
    cudaEventRecord(px.eCSR, SC);

    auto gemm = [&](cudaStream_t s, int l, int t, const float* src, int din) {
        const float* Wt = Wl[l] + (size_t)t * din * 64;
        if (din == 128)
            gemm_kernel<128, false><<<gblocks, 256, SMEM128, s>>>(hw(t), src, Wt, N);
        else
            gemm_kernel<64, true><<<gblocks, 256, SMEM64, s>>>(hw(t), src, Wt, N);
    };

    float* dsts[4] = {A1, AE1, B, C};
    for (int l = 0; l < 5; l++) {
        const float* p0;
        const float* p1;
        int din = (l == 0) ? 128 : 64;
        if (l == 0) { p0 = feat0; p1 = feat1; }
        else        { p0 = dsts[l - 1]; p1 = dsts[l - 1] + half; }

        // ----- S0 chain: G0(p0), [p1 ready] G1(p1), A01 -----
        gemm(S0, l, 0, p0, din);
        if (l > 0) cudaStreamWaitEvent(S0, px.e1[l - 1], 0);
        gemm(S0, l, 1, p1, din);
        if (l == 0) cudaStreamWaitEvent(S0, px.eCSR, 0);
        // ----- S1 chain: G3(p1), [p0 ready] G2(p0), A23 -----
        gemm(S1, l, 3, p1, din);
        if (l > 0) cudaStreamWaitEvent(S1, px.e0[l - 1], 0);
        gemm(S1, l, 2, p0, din);
        if (l == 0) cudaStreamWaitEvent(S1, px.eCSR, 0);

        if (l < 4) {
            float* dst = dsts[l];
            agg2_kernel<<<ablocks, 256, 0, S0>>>((float4*)dst,
                (const uint4*)hw(0), (const uint4*)hw(1), rp(0), cvp(0), rp(1), cvp(1), N);
            cudaEventRecord(px.e0[l], S0);
            agg2_kernel<<<ablocks, 256, 0, S1>>>((float4*)(dst + half),
                (const uint4*)hw(2), (const uint4*)hw(3), rp(2), cvp(2), rp(3), cvp(3), N);
            cudaEventRecord(px.e1[l], S1);
        } else {
            agg2_final_kernel<<<ablocks, 256, 0, S0>>>(out,
                (const float4*)A1, (const float4*)AE1,
                (const uint4*)hw(0), (const uint4*)hw(1),
                rp(0), cvp(0), rp(1), cvp(1), att, N);
            cudaEventRecord(px.e0[l], S0);
            agg2_final_kernel<<<ablocks, 256, 0, S1>>>(out + (size_t)N * 192,
                (const float4*)(A1 + half), (const float4*)(AE1 + half),
                (const uint4*)hw(2), (const uint4*)hw(3),
                rp(2), cvp(2), rp(3), cvp(3), att, N);
            cudaEventRecord(px.e1[l], S1);
        }
    }

    // ---- join back to capture-origin stream ----
    cudaStreamWaitEvent(S0, px.e1[4], 0);
}

// round 13
// speedup vs baseline: 1.8122x; 1.1995x over previous
#include <cuda_runtime.h>
#include <cuda_fp16.h>
#include <cstdint>

#define MAXN 100000
#define MAXE 1000000
#define HDIM 64

// ---------------------------------------------------------------------------
// Static device scratch (no allocation allowed)
// ---------------------------------------------------------------------------
__device__ float  g_A1 [2 * MAXN * HDIM];   // layer1 pre-act (fp32)
__device__ float  g_AE1[2 * MAXN * HDIM];   // layer2 pre-act (fp32)
__device__ float  g_B  [2 * MAXN * HDIM];   // layer3 pre-act (fp32)
__device__ float  g_C  [2 * MAXN * HDIM];   // layer4 pre-act (fp32)
__device__ __half g_HW [4 * MAXN * HDIM];   // GEMM outputs fp16 (gather-only)
__device__ int    g_cnt   [4 * MAXN];
__device__ int    g_rowptr[4 * (MAXN + 1)];
__device__ int    g_rowofs[4 * MAXN];
__device__ int2   g_cv    [4 * MAXE];
__device__ int    g_part  [4 * 512];

// ---------------------------------------------------------------------------
// Tensor-core GEMM via mma.sync (HMMA, baseline PTX — NOT tcgen05):
//   hw[N,64](fp16) = act(h)[N,DIN](fp32->fp16) @ W[DIN,64](fp32->fp16), fp32 acc
// 256 threads = 8 warps; CTA tile 128 rows x 64 cols; warp tile m16 x n64.
// A fragments via ldmatrix.x4; B fragments via direct LDS.32 from W^T.
// Padded smem stride (DIN+8 halves) => conflict-free for both paths.
// ---------------------------------------------------------------------------
template <int DIN, bool RELU>
__global__ __launch_bounds__(256) void gemm_mma_kernel(
    __half* __restrict__ out, const float* __restrict__ h,
    const float* __restrict__ W, int N) {
    constexpr int STRIDE = DIN + 8;  // halves
    extern __shared__ __half smem_h[];
    __half* Ah = smem_h;                     // [128][STRIDE]
    __half* Wt = smem_h + 128 * STRIDE;      // [64][STRIDE]  (W transposed: Wt[n][k])

    const int tid  = threadIdx.x;
    const int warp = tid >> 5;
    const int lane = tid & 31;
    const int row0 = blockIdx.x * 128;

    // Stage A: h fp32 -> fp16, relu fused
    const int VPR = DIN / 4;
    for (int i = tid; i < 128 * VPR; i += 256) {
        int r = i / VPR, kc = i % VPR;
        int gr = row0 + r;
        float4 v = make_float4(0.f, 0.f, 0.f, 0.f);
        if (gr < N) v = reinterpret_cast<const float4*>(h)[(size_t)gr * VPR + kc];
        if (RELU) {
            v.x = fmaxf(v.x, 0.f); v.y = fmaxf(v.y, 0.f);
            v.z = fmaxf(v.z, 0.f); v.w = fmaxf(v.w, 0.f);
        }
        __half2 h01 = __floats2half2_rn(v.x, v.y);
        __half2 h23 = __floats2half2_rn(v.z, v.w);
        *reinterpret_cast<uint2*>(&Ah[r * STRIDE + kc * 4]) =
            make_uint2(*reinterpret_cast<uint32_t*>(&h01),
                       *reinterpret_cast<uint32_t*>(&h23));
    }
    // Stage B: W[k][n] fp32 -> Wt[n][k] fp16
    for (int i = tid; i < DIN * 64; i += 256) {
        int k = i >> 6, n = i & 63;
        Wt[n * STRIDE + k] = __float2half_rn(__ldg(W + i));
    }
    __syncthreads();

    const int g  = lane >> 2;   // 0..7
    const int tq = lane & 3;    // 0..3
    const int mrow = warp * 16;

    float acc[8][4];
#pragma unroll
    for (int nt = 0; nt < 8; nt++)
#pragma unroll
        for (int j = 0; j < 4; j++) acc[nt][j] = 0.f;

    // ldmatrix source row for this lane (constant across ksteps except k offset)
    const int mm  = (lane & 7) + ((lane >> 3) & 1) * 8;
    const int kof = (lane >> 4) * 8;

#pragma unroll
    for (int ks = 0; ks < DIN / 16; ks++) {
        uint32_t a0, a1, a2, a3;
        {
            uint32_t aaddr = (uint32_t)__cvta_generic_to_shared(
                &Ah[(mrow + mm) * STRIDE + ks * 16 + kof]);
            asm volatile(
                "ldmatrix.sync.aligned.m8n8.x4.shared.b16 {%0,%1,%2,%3}, [%4];"
                : "=r"(a0), "=r"(a1), "=r"(a2), "=r"(a3) : "r"(aaddr));
        }
        const int k0 = ks * 16 + tq * 2;
#pragma unroll
        for (int nt = 0; nt < 8; nt++) {
            int n = nt * 8 + g;
            uint32_t b0 = *reinterpret_cast<const uint32_t*>(&Wt[n * STRIDE + k0]);
            uint32_t b1 = *reinterpret_cast<const uint32_t*>(&Wt[n * STRIDE + k0 + 8]);
            asm volatile(
                "mma.sync.aligned.m16n8k16.row.col.f32.f16.f16.f32 "
                "{%0,%1,%2,%3}, {%4,%5,%6,%7}, {%8,%9}, {%0,%1,%2,%3};"
                : "+f"(acc[nt][0]), "+f"(acc[nt][1]), "+f"(acc[nt][2]), "+f"(acc[nt][3])
                : "r"(a0), "r"(a1), "r"(a2), "r"(a3), "r"(b0), "r"(b1));
        }
    }

    // Epilogue: c-frag rows g, g+8; cols tq*2, tq*2+1 per n-tile -> fp16 stores
    const int r0 = row0 + mrow + g;
    const int r1 = r0 + 8;
#pragma unroll
    for (int nt = 0; nt < 8; nt++) {
        int cb = nt * 8 + tq * 2;
        if (r0 < N) {
            __half2 hv = __floats2half2_rn(acc[nt][0], acc[nt][1]);
            *reinterpret_cast<uint32_t*>(&out[(size_t)r0 * 64 + cb]) =
                *reinterpret_cast<uint32_t*>(&hv);
        }
        if (r1 < N) {
            __half2 hv = __floats2half2_rn(acc[nt][2], acc[nt][3]);
            *reinterpret_cast<uint32_t*>(&out[(size_t)r1 * 64 + cb]) =
                *reinterpret_cast<uint32_t*>(&hv);
        }
    }
}

// ---------------------------------------------------------------------------
// CSR build kernels
// ---------------------------------------------------------------------------
__global__ void hist_kernel(int* __restrict__ cnt, const int* __restrict__ rows,
                            int E, int N) {
    int i = blockIdx.x * blockDim.x + threadIdx.x;
    if (i >= 4 * E) return;
    int t = i / E;
    atomicAdd(&cnt[t * N + __ldg(rows + i)], 1);
}

__global__ void scan_phase1(const int* __restrict__ cnt, int* __restrict__ part,
                            int N, int nb) {
    int t = blockIdx.y, b = blockIdx.x;
    int i = b * 256 + threadIdx.x;
    int v = (i < N) ? cnt[t * N + i] : 0;
#pragma unroll
    for (int o = 16; o; o >>= 1) v += __shfl_down_sync(0xffffffffu, v, o);
    __shared__ int ws[8];
    if ((threadIdx.x & 31) == 0) ws[threadIdx.x >> 5] = v;
    __syncthreads();
    if (threadIdx.x == 0) {
        int s = 0;
#pragma unroll
        for (int j = 0; j < 8; j++) s += ws[j];
        part[t * nb + b] = s;
    }
}

__global__ void scan_phase2(int* __restrict__ part, int* __restrict__ rowptr,
                            int nb, int N, int E) {
    int t = threadIdx.x;
    if (t >= 4) return;
    int s = 0;
    for (int b = 0; b < nb; b++) {
        int v = part[t * nb + b];
        part[t * nb + b] = s;
        s += v;
    }
    rowptr[t * (N + 1) + N] = E;
}

__global__ void scan_phase3(const int* __restrict__ cnt, const int* __restrict__ part,
                            int* __restrict__ rowptr, int* __restrict__ rowofs,
                            int N, int nb) {
    int t = blockIdx.y, b = blockIdx.x;
    int i = b * 256 + threadIdx.x;
    int v = (i < N) ? cnt[t * N + i] : 0;
    __shared__ int sm[256];
    sm[threadIdx.x] = v;
    __syncthreads();
#pragma unroll
    for (int o = 1; o < 256; o <<= 1) {
        int x = (threadIdx.x >= o) ? sm[threadIdx.x - o] : 0;
        __syncthreads();
        sm[threadIdx.x] += x;
        __syncthreads();
    }
    if (i < N) {
        int excl = sm[threadIdx.x] - v + part[t * nb + b];
        rowptr[t * (N + 1) + i] = excl;
        rowofs[t * N + i] = excl;
    }
}

__global__ void fill_kernel(int2* __restrict__ cv, int* __restrict__ rowofs,
                            const int* __restrict__ rows, const int* __restrict__ cols,
                            const float* __restrict__ vals, int E, int N) {
    int i = blockIdx.x * blockDim.x + threadIdx.x;
    if (i >= 4 * E) return;
    int t = i / E;
    int r = __ldg(rows + i);
    int pos = atomicAdd(&rowofs[t * N + r], 1);
    cv[(size_t)t * E + pos] = make_int2(__ldg(cols + i), __float_as_int(__ldg(vals + i)));
}

// ---------------------------------------------------------------------------
// CSR aggregation over fp16 hw: 8 lanes/row, 16B per lane, fp32 accumulate
// ---------------------------------------------------------------------------
__device__ __forceinline__ void fma8(float acc[8], float v, uint4 x) {
    const __half2* h = reinterpret_cast<const __half2*>(&x);
#pragma unroll
    for (int i = 0; i < 4; i++) {
        float2 f = __half22float2(h[i]);
        acc[2 * i]     = fmaf(v, f.x, acc[2 * i]);
        acc[2 * i + 1] = fmaf(v, f.y, acc[2 * i + 1]);
    }
}

__device__ __forceinline__ void agg_one(float acc0[8], float acc1[8],
                                        const uint4* __restrict__ hw,
                                        const int* __restrict__ rp,
                                        const int2* __restrict__ cv, int r, int c) {
    int b = __ldg(rp + r);
    int e = __ldg(rp + r + 1);
    for (; b + 4 <= e; b += 4) {
        int2 p0 = __ldg(cv + b);
        int2 p1 = __ldg(cv + b + 1);
        int2 p2 = __ldg(cv + b + 2);
        int2 p3 = __ldg(cv + b + 3);
        uint4 x0 = __ldg(hw + (size_t)p0.x * 8 + c);
        uint4 x1 = __ldg(hw + (size_t)p1.x * 8 + c);
        uint4 x2 = __ldg(hw + (size_t)p2.x * 8 + c);
        uint4 x3 = __ldg(hw + (size_t)p3.x * 8 + c);
        fma8(acc0, __int_as_float(p0.y), x0);
        fma8(acc1, __int_as_float(p1.y), x1);
        fma8(acc0, __int_as_float(p2.y), x2);
        fma8(acc1, __int_as_float(p3.y), x3);
    }
    for (; b < e; b++) {
        int2 p = __ldg(cv + b);
        uint4 x = __ldg(hw + (size_t)p.x * 8 + c);
        fma8(acc0, __int_as_float(p.y), x);
    }
}

__global__ __launch_bounds__(256) void agg2_kernel(
    float4* __restrict__ out,
    const uint4* __restrict__ hw0, const uint4* __restrict__ hw1,
    const int* __restrict__ rp0, const int2* __restrict__ cv0,
    const int* __restrict__ rp1, const int2* __restrict__ cv1, int N) {
    int gid = blockIdx.x * blockDim.x + threadIdx.x;
    if (gid >= N * 8) return;
    int r = gid >> 3, c = gid & 7;
    float acc0[8], acc1[8];
#pragma unroll
    for (int i = 0; i < 8; i++) { acc0[i] = 0.f; acc1[i] = 0.f; }
    agg_one(acc0, acc1, hw0, rp0, cv0, r, c);
    agg_one(acc0, acc1, hw1, rp1, cv1, r, c);
    float4 v0 = make_float4(acc0[0] + acc1[0], acc0[1] + acc1[1],
                            acc0[2] + acc1[2], acc0[3] + acc1[3]);
    float4 v1 = make_float4(acc0[4] + acc1[4], acc0[5] + acc1[5],
                            acc0[6] + acc1[6], acc0[7] + acc1[7]);
    out[(size_t)r * 16 + c * 2]     = v0;
    out[(size_t)r * 16 + c * 2 + 1] = v1;
}

// Layer-5 agg fused with the final attention-concat epilogue (one node class).
__global__ __launch_bounds__(256) void agg2_final_kernel(
    float* __restrict__ out,
    const float4* __restrict__ A1, const float4* __restrict__ AE1,
    const uint4* __restrict__ hw0, const uint4* __restrict__ hw1,
    const int* __restrict__ rp0, const int2* __restrict__ cv0,
    const int* __restrict__ rp1, const int2* __restrict__ cv1,
    const float* __restrict__ att, int N) {
    int gid = blockIdx.x * blockDim.x + threadIdx.x;
    if (gid >= N * 8) return;
    int r = gid >> 3, c = gid & 7;

    float acc0[8], acc1[8];
#pragma unroll
    for (int i = 0; i < 8; i++) { acc0[i] = 0.f; acc1[i] = 0.f; }
    agg_one(acc0, acc1, hw0, rp0, cv0, r, c);
    agg_one(acc0, acc1, hw1, rp1, cv1, r, c);

    float a0 = __ldg(att + 0), a1 = __ldg(att + 1), a2 = __ldg(att + 2);

    float4 x1a = A1[(size_t)r * 16 + c * 2];
    float4 x1b = A1[(size_t)r * 16 + c * 2 + 1];
    x1a.x = fmaxf(x1a.x, 0.f); x1a.y = fmaxf(x1a.y, 0.f);
    x1a.z = fmaxf(x1a.z, 0.f); x1a.w = fmaxf(x1a.w, 0.f);
    x1b.x = fmaxf(x1b.x, 0.f); x1b.y = fmaxf(x1b.y, 0.f);
    x1b.z = fmaxf(x1b.z, 0.f); x1b.w = fmaxf(x1b.w, 0.f);

    float4 xea = AE1[(size_t)r * 16 + c * 2];
    float4 xeb = AE1[(size_t)r * 16 + c * 2 + 1];
    xea.x = fmaxf(xea.x, 0.f); xea.y = fmaxf(xea.y, 0.f);
    xea.z = fmaxf(xea.z, 0.f); xea.w = fmaxf(xea.w, 0.f);
    xeb.x = fmaxf(xeb.x, 0.f); xeb.y = fmaxf(xeb.y, 0.f);
    xeb.z = fmaxf(xeb.z, 0.f); xeb.w = fmaxf(xeb.w, 0.f);

    float* o = out + (size_t)r * 192 + (size_t)c * 8;
    reinterpret_cast<float4*>(o)[0] =
        make_float4(x1a.x * a0, x1a.y * a0, x1a.z * a0, x1a.w * a0);
    reinterpret_cast<float4*>(o + 4)[0] =
        make_float4(x1b.x * a0, x1b.y * a0, x1b.z * a0, x1b.w * a0);
    reinterpret_cast<float4*>(o + 64)[0] =
        make_float4(xea.x * a1, xea.y * a1, xea.z * a1, xea.w * a1);
    reinterpret_cast<float4*>(o + 68)[0] =
        make_float4(xeb.x * a1, xeb.y * a1, xeb.z * a1, xeb.w * a1);
    reinterpret_cast<float4*>(o + 128)[0] =
        make_float4((acc0[0] + acc1[0] + x1a.x) * a2, (acc0[1] + acc1[1] + x1a.y) * a2,
                    (acc0[2] + acc1[2] + x1a.z) * a2, (acc0[3] + acc1[3] + x1a.w) * a2);
    reinterpret_cast<float4*>(o + 132)[0] =
        make_float4((acc0[4] + acc1[4] + x1b.x) * a2, (acc0[5] + acc1[5] + x1b.y) * a2,
                    (acc0[6] + acc1[6] + x1b.z) * a2, (acc0[7] + acc1[7] + x1b.w) * a2);
}

// ---------------------------------------------------------------------------
// Host launcher — R12 schedule (best: 1010 µs): R7 symmetric fork + CSR on SC
// + fused layer-5 final; GEMMs swapped to mma.sync tensor path.
// ---------------------------------------------------------------------------
struct PipeCtx {
    cudaStream_t s1, sc;
    cudaEvent_t efork, eCSR;
    cudaEvent_t e0[5];
    cudaEvent_t e1[5];
    PipeCtx() {
        cudaStreamCreateWithFlags(&s1, cudaStreamNonBlocking);
        cudaStreamCreateWithFlags(&sc, cudaStreamNonBlocking);
        cudaEventCreateWithFlags(&efork, cudaEventDisableTiming);
        cudaEventCreateWithFlags(&eCSR,  cudaEventDisableTiming);
        for (int i = 0; i < 5; i++) {
            cudaEventCreateWithFlags(&e0[i], cudaEventDisableTiming);
            cudaEventCreateWithFlags(&e1[i], cudaEventDisableTiming);
        }
    }
};
static PipeCtx& pipe_ctx() { static PipeCtx c; return c; }

extern "C" void kernel_launch(void* const* d_in, const int* in_sizes, int n_in,
                              void* d_out, int out_size) {
    const float* feat0 = (const float*)d_in[0];
    const float* feat1 = (const float*)d_in[1];
    const int*   rows  = (const int*)  d_in[2];
    const int*   cols  = (const int*)  d_in[3];
    const float* vals  = (const float*)d_in[4];
    const float* Wl[5] = {(const float*)d_in[5], (const float*)d_in[6], (const float*)d_in[7],
                          (const float*)d_in[8], (const float*)d_in[9]};
    const float* att   = (const float*)d_in[10];
    float* out = (float*)d_out;

    const int N = in_sizes[0] / 128;   // 100000
    const int E = in_sizes[2] / 4;     // 1000000

    float *A1, *AE1, *B, *C;
    __half* HW;
    int *cnt, *rowptr, *rowofs, *part;
    int2* cv;
    cudaGetSymbolAddress((void**)&A1,     g_A1);
    cudaGetSymbolAddress((void**)&AE1,    g_AE1);
    cudaGetSymbolAddress((void**)&B,      g_B);
    cudaGetSymbolAddress((void**)&C,      g_C);
    cudaGetSymbolAddress((void**)&HW,     g_HW);
    cudaGetSymbolAddress((void**)&cnt,    g_cnt);
    cudaGetSymbolAddress((void**)&rowptr, g_rowptr);
    cudaGetSymbolAddress((void**)&rowofs, g_rowofs);
    cudaGetSymbolAddress((void**)&cv,     g_cv);
    cudaGetSymbolAddress((void**)&part,   g_part);

    const int SMEM64  = (128 * (64 + 8)  + 64 * (64 + 8))  * 2;  // 27648 B
    const int SMEM128 = (128 * (128 + 8) + 64 * (128 + 8)) * 2;  // 52224 B
    cudaFuncSetAttribute(gemm_mma_kernel<128, false>,
                         cudaFuncAttributeMaxDynamicSharedMemorySize, SMEM128);
    cudaFuncSetAttribute(gemm_mma_kernel<64, true>,
                         cudaFuncAttributeMaxDynamicSharedMemorySize, SMEM64);

    PipeCtx& px = pipe_ctx();
    cudaStream_t S0 = 0, S1 = px.s1, SC = px.sc;

    const int gblocks = (N + 127) / 128;
    const int ablocks = (N * 8 + 255) / 256;
    const size_t half = (size_t)N * 64;

    auto rp  = [&](int t) { return rowptr + (size_t)t * (N + 1); };
    auto cvp = [&](int t) { return cv + (size_t)t * E; };
    auto hw  = [&](int t) { return HW + (size_t)t * half; };

    // ---- fork ----
    cudaEventRecord(px.efork, S0);
    cudaStreamWaitEvent(S1, px.efork, 0);
    cudaStreamWaitEvent(SC, px.efork, 0);

    // ---- CSR build on SC ----
    const int nb = (N + 255) / 256;
    cudaMemsetAsync(cnt, 0, (size_t)4 * N * sizeof(int), SC);
    {
        int blocks = (4 * E + 255) / 256;
        hist_kernel<<<blocks, 256, 0, SC>>>(cnt, rows, E, N);
        scan_phase1<<<dim3(nb, 4), 256, 0, SC>>>(cnt, part, N, nb);
        scan_phase2<<<1, 32, 0, SC>>>(part, rowptr, nb, N, E);
        scan_phase3<<<dim3(nb, 4), 256, 0, SC>>>(cnt, part, rowptr, rowofs, N, nb);
        fill_kernel<<<blocks, 256, 0, SC>>>(cv, rowofs, rows, cols, vals, E, N);
    }
    cudaEventRecord(px.eCSR, SC);

    auto gemm = [&](cudaStream_t s, int l, int t, const float* src, int din) {
        const float* Wt = Wl[l] + (size_t)t * din * 64;
        if (din == 128)
            gemm_mma_kernel<128, false><<<gblocks, 256, SMEM128, s>>>(hw(t), src, Wt, N);
        else
            gemm_mma_kernel<64, true><<<gblocks, 256, SMEM64, s>>>(hw(t), src, Wt, N);
    };

    float* dsts[4] = {A1, AE1, B, C};
    for (int l = 0; l < 5; l++) {
        const float* p0;
        const float* p1;
        int din = (l == 0) ? 128 : 64;
        if (l == 0) { p0 = feat0; p1 = feat1; }
        else        { p0 = dsts[l - 1]; p1 = dsts[l - 1] + half; }

        // ----- S0 chain: G0(p0), [p1 ready] G1(p1), A01 -----
        gemm(S0, l, 0, p0, din);
        if (l > 0) cudaStreamWaitEvent(S0, px.e1[l - 1], 0);
        gemm(S0, l, 1, p1, din);
        if (l == 0) cudaStreamWaitEvent(S0, px.eCSR, 0);
        // ----- S1 chain: G3(p1), [p0 ready] G2(p0), A23 -----
        gemm(S1, l, 3, p1, din);
        if (l > 0) cudaStreamWaitEvent(S1, px.e0[l - 1], 0);
        gemm(S1, l, 2, p0, din);
        if (l == 0) cudaStreamWaitEvent(S1, px.eCSR, 0);

        if (l < 4) {
            float* dst = dsts[l];
            agg2_kernel<<<ablocks, 256, 0, S0>>>((float4*)dst,
                (const uint4*)hw(0), (const uint4*)hw(1), rp(0), cvp(0), rp(1), cvp(1), N);
            cudaEventRecord(px.e0[l], S0);
            agg2_kernel<<<ablocks, 256, 0, S1>>>((float4*)(dst + half),
                (const uint4*)hw(2), (const uint4*)hw(3), rp(2), cvp(2), rp(3), cvp(3), N);
            cudaEventRecord(px.e1[l], S1);
        } else {
            agg2_final_kernel<<<ablocks, 256, 0, S0>>>(out,
                (const float4*)A1, (const float4*)AE1,
                (const uint4*)hw(0), (const uint4*)hw(1),
                rp(0), cvp(0), rp(1), cvp(1), att, N);
            cudaEventRecord(px.e0[l], S0);
            agg2_final_kernel<<<ablocks, 256, 0, S1>>>(out + (size_t)N * 192,
                (const float4*)(A1 + half), (const float4*)(AE1 + half),
                (const uint4*)hw(2), (const uint4*)hw(3),
                rp(2), cvp(2), rp(3), cvp(3), att, N);
            cudaEventRecord(px.e1[l], S1);
        }
    }

    // ---- join back to capture-origin stream ----
    cudaStreamWaitEvent(S0, px.e1[4], 0);
}

// round 14
// speedup vs baseline: 1.9245x; 1.0620x over previous
#include <cuda_runtime.h>
#include <cuda_fp16.h>
#include <cstdint>

#define MAXN 100000
#define MAXE 1000000
#define HDIM 64

// ---------------------------------------------------------------------------
// Static device scratch (no allocation allowed)
// All hidden states fp16, relu pre-applied. P (layer5) never materialized.
// ---------------------------------------------------------------------------
__device__ __half g_A1 [2 * MAXN * HDIM];   // relu(layer1 out)
__device__ __half g_AE1[2 * MAXN * HDIM];   // relu(layer2 out)
__device__ __half g_B  [2 * MAXN * HDIM];   // relu(layer3 out)
__device__ __half g_C  [2 * MAXN * HDIM];   // relu(layer4 out)
__device__ __half g_HW [4 * MAXN * HDIM];   // GEMM outputs fp16 (gather-only)
__device__ int    g_cnt   [4 * MAXN];
__device__ int    g_rowptr[4 * (MAXN + 1)];
__device__ int    g_rowofs[4 * MAXN];
__device__ int2   g_cv    [4 * MAXE];
__device__ int    g_part  [4 * 512];

// ---------------------------------------------------------------------------
// Tensor-core GEMM via mma.sync (HMMA, baseline PTX):
//   hw[N,64](fp16) = in[N,DIN] @ W[DIN,64](fp32->fp16), fp32 accumulate
// HALF_IN: input already fp16 + relu'd (layers 2-5). Else fp32 (layer 1 feat).
// 256 threads = 8 warps; CTA tile 128 x 64; warp tile m16 x n64.
// ---------------------------------------------------------------------------
template <int DIN, bool HALF_IN>
__global__ __launch_bounds__(256) void gemm_mma_kernel(
    __half* __restrict__ out, const void* __restrict__ hvoid,
    const float* __restrict__ W, int N) {
    constexpr int STRIDE = DIN + 8;  // halves
    extern __shared__ __half smem_h[];
    __half* Ah = smem_h;                     // [128][STRIDE]
    __half* Wt = smem_h + 128 * STRIDE;      // [64][STRIDE]  (Wt[n][k])

    const int tid  = threadIdx.x;
    const int warp = tid >> 5;
    const int lane = tid & 31;
    const int row0 = blockIdx.x * 128;

    if (HALF_IN) {
        const __half* h = (const __half*)hvoid;
        constexpr int V8 = DIN / 8;  // uint4 (8 halves) per row
        for (int i = tid; i < 128 * V8; i += 256) {
            int r = i / V8, kc = i % V8;
            int gr = row0 + r;
            uint4 v = make_uint4(0u, 0u, 0u, 0u);
            if (gr < N) v = reinterpret_cast<const uint4*>(h)[(size_t)gr * V8 + kc];
            *reinterpret_cast<uint4*>(&Ah[r * STRIDE + kc * 8]) = v;
        }
    } else {
        const float* h = (const float*)hvoid;
        constexpr int V4 = DIN / 4;
        for (int i = tid; i < 128 * V4; i += 256) {
            int r = i / V4, kc = i % V4;
            int gr = row0 + r;
            float4 v = make_float4(0.f, 0.f, 0.f, 0.f);
            if (gr < N) v = reinterpret_cast<const float4*>(h)[(size_t)gr * V4 + kc];
            __half2 h01 = __floats2half2_rn(v.x, v.y);
            __half2 h23 = __floats2half2_rn(v.z, v.w);
            *reinterpret_cast<uint2*>(&Ah[r * STRIDE + kc * 4]) =
                make_uint2(*reinterpret_cast<uint32_t*>(&h01),
                           *reinterpret_cast<uint32_t*>(&h23));
        }
    }
    // Stage B: W[k][n] fp32 -> Wt[n][k] fp16
    for (int i = tid; i < DIN * 64; i += 256) {
        int k = i >> 6, n = i & 63;
        Wt[n * STRIDE + k] = __float2half_rn(__ldg(W + i));
    }
    __syncthreads();

    const int g  = lane >> 2;
    const int tq = lane & 3;
    const int mrow = warp * 16;

    float acc[8][4];
#pragma unroll
    for (int nt = 0; nt < 8; nt++)
#pragma unroll
        for (int j = 0; j < 4; j++) acc[nt][j] = 0.f;

    const int mm  = (lane & 7) + ((lane >> 3) & 1) * 8;
    const int kof = (lane >> 4) * 8;

#pragma unroll
    for (int ks = 0; ks < DIN / 16; ks++) {
        uint32_t a0, a1, a2, a3;
        {
            uint32_t aaddr = (uint32_t)__cvta_generic_to_shared(
                &Ah[(mrow + mm) * STRIDE + ks * 16 + kof]);
            asm volatile(
                "ldmatrix.sync.aligned.m8n8.x4.shared.b16 {%0,%1,%2,%3}, [%4];"
                : "=r"(a0), "=r"(a1), "=r"(a2), "=r"(a3) : "r"(aaddr));
        }
        const int k0 = ks * 16 + tq * 2;
#pragma unroll
        for (int nt = 0; nt < 8; nt++) {
            int n = nt * 8 + g;
            uint32_t b0 = *reinterpret_cast<const uint32_t*>(&Wt[n * STRIDE + k0]);
            uint32_t b1 = *reinterpret_cast<const uint32_t*>(&Wt[n * STRIDE + k0 + 8]);
            asm volatile(
                "mma.sync.aligned.m16n8k16.row.col.f32.f16.f16.f32 "
                "{%0,%1,%2,%3}, {%4,%5,%6,%7}, {%8,%9}, {%0,%1,%2,%3};"
                : "+f"(acc[nt][0]), "+f"(acc[nt][1]), "+f"(acc[nt][2]), "+f"(acc[nt][3])
                : "r"(a0), "r"(a1), "r"(a2), "r"(a3), "r"(b0), "r"(b1));
        }
    }

    const int r0 = row0 + mrow + g;
    const int r1 = r0 + 8;
#pragma unroll
    for (int nt = 0; nt < 8; nt++) {
        int cb = nt * 8 + tq * 2;
        if (r0 < N) {
            __half2 hv = __floats2half2_rn(acc[nt][0], acc[nt][1]);
            *reinterpret_cast<uint32_t*>(&out[(size_t)r0 * 64 + cb]) =
                *reinterpret_cast<uint32_t*>(&hv);
        }
        if (r1 < N) {
            __half2 hv = __floats2half2_rn(acc[nt][2], acc[nt][3]);
            *reinterpret_cast<uint32_t*>(&out[(size_t)r1 * 64 + cb]) =
                *reinterpret_cast<uint32_t*>(&hv);
        }
    }
}

// ---------------------------------------------------------------------------
// CSR build kernels
// ---------------------------------------------------------------------------
__global__ void hist_kernel(int* __restrict__ cnt, const int* __restrict__ rows,
                            int E, int N) {
    int i = blockIdx.x * blockDim.x + threadIdx.x;
    if (i >= 4 * E) return;
    int t = i / E;
    atomicAdd(&cnt[t * N + __ldg(rows + i)], 1);
}

__global__ void scan_phase1(const int* __restrict__ cnt, int* __restrict__ part,
                            int N, int nb) {
    int t = blockIdx.y, b = blockIdx.x;
    int i = b * 256 + threadIdx.x;
    int v = (i < N) ? cnt[t * N + i] : 0;
#pragma unroll
    for (int o = 16; o; o >>= 1) v += __shfl_down_sync(0xffffffffu, v, o);
    __shared__ int ws[8];
    if ((threadIdx.x & 31) == 0) ws[threadIdx.x >> 5] = v;
    __syncthreads();
    if (threadIdx.x == 0) {
        int s = 0;
#pragma unroll
        for (int j = 0; j < 8; j++) s += ws[j];
        part[t * nb + b] = s;
    }
}

__global__ void scan_phase2(int* __restrict__ part, int* __restrict__ rowptr,
                            int nb, int N, int E) {
    int t = threadIdx.x;
    if (t >= 4) return;
    int s = 0;
    for (int b = 0; b < nb; b++) {
        int v = part[t * nb + b];
        part[t * nb + b] = s;
        s += v;
    }
    rowptr[t * (N + 1) + N] = E;
}

__global__ void scan_phase3(const int* __restrict__ cnt, const int* __restrict__ part,
                            int* __restrict__ rowptr, int* __restrict__ rowofs,
                            int N, int nb) {
    int t = blockIdx.y, b = blockIdx.x;
    int i = b * 256 + threadIdx.x;
    int v = (i < N) ? cnt[t * N + i] : 0;
    __shared__ int sm[256];
    sm[threadIdx.x] = v;
    __syncthreads();
#pragma unroll
    for (int o = 1; o < 256; o <<= 1) {
        int x = (threadIdx.x >= o) ? sm[threadIdx.x - o] : 0;
        __syncthreads();
        sm[threadIdx.x] += x;
        __syncthreads();
    }
    if (i < N) {
        int excl = sm[threadIdx.x] - v + part[t * nb + b];
        rowptr[t * (N + 1) + i] = excl;
        rowofs[t * N + i] = excl;
    }
}

__global__ void fill_kernel(int2* __restrict__ cv, int* __restrict__ rowofs,
                            const int* __restrict__ rows, const int* __restrict__ cols,
                            const float* __restrict__ vals, int E, int N) {
    int i = blockIdx.x * blockDim.x + threadIdx.x;
    if (i >= 4 * E) return;
    int t = i / E;
    int r = __ldg(rows + i);
    int pos = atomicAdd(&rowofs[t * N + r], 1);
    cv[(size_t)t * E + pos] = make_int2(__ldg(cols + i), __float_as_int(__ldg(vals + i)));
}

// ---------------------------------------------------------------------------
// CSR aggregation over fp16 hw: 8 lanes/row, 16B per lane, fp32 accumulate
// ---------------------------------------------------------------------------
__device__ __forceinline__ void fma8(float acc[8], float v, uint4 x) {
    const __half2* h = reinterpret_cast<const __half2*>(&x);
#pragma unroll
    for (int i = 0; i < 4; i++) {
        float2 f = __half22float2(h[i]);
        acc[2 * i]     = fmaf(v, f.x, acc[2 * i]);
        acc[2 * i + 1] = fmaf(v, f.y, acc[2 * i + 1]);
    }
}

__device__ __forceinline__ void agg_one(float acc0[8], float acc1[8],
                                        const uint4* __restrict__ hw,
                                        const int* __restrict__ rp,
                                        const int2* __restrict__ cv, int r, int c) {
    int b = __ldg(rp + r);
    int e = __ldg(rp + r + 1);
    for (; b + 4 <= e; b += 4) {
        int2 p0 = __ldg(cv + b);
        int2 p1 = __ldg(cv + b + 1);
        int2 p2 = __ldg(cv + b + 2);
        int2 p3 = __ldg(cv + b + 3);
        uint4 x0 = __ldg(hw + (size_t)p0.x * 8 + c);
        uint4 x1 = __ldg(hw + (size_t)p1.x * 8 + c);
        uint4 x2 = __ldg(hw + (size_t)p2.x * 8 + c);
        uint4 x3 = __ldg(hw + (size_t)p3.x * 8 + c);
        fma8(acc0, __int_as_float(p0.y), x0);
        fma8(acc1, __int_as_float(p1.y), x1);
        fma8(acc0, __int_as_float(p2.y), x2);
        fma8(acc1, __int_as_float(p3.y), x3);
    }
    for (; b < e; b++) {
        int2 p = __ldg(cv + b);
        uint4 x = __ldg(hw + (size_t)p.x * 8 + c);
        fma8(acc0, __int_as_float(p.y), x);
    }
}

// Aggregation with fused relu, fp16 output (layers 1-4 hidden states)
__global__ __launch_bounds__(256) void agg2_relu_h_kernel(
    uint4* __restrict__ out,
    const uint4* __restrict__ hw0, const uint4* __restrict__ hw1,
    const int* __restrict__ rp0, const int2* __restrict__ cv0,
    const int* __restrict__ rp1, const int2* __restrict__ cv1, int N) {
    int gid = blockIdx.x * blockDim.x + threadIdx.x;
    if (gid >= N * 8) return;
    int r = gid >> 3, c = gid & 7;
    float acc0[8], acc1[8];
#pragma unroll
    for (int i = 0; i < 8; i++) { acc0[i] = 0.f; acc1[i] = 0.f; }
    agg_one(acc0, acc1, hw0, rp0, cv0, r, c);
    agg_one(acc0, acc1, hw1, rp1, cv1, r, c);
    __half2 h[4];
#pragma unroll
    for (int i = 0; i < 4; i++) {
        float lo = fmaxf(acc0[2 * i]     + acc1[2 * i],     0.f);
        float hi = fmaxf(acc0[2 * i + 1] + acc1[2 * i + 1], 0.f);
        h[i] = __floats2half2_rn(lo, hi);
    }
    out[(size_t)r * 8 + c] = *reinterpret_cast<uint4*>(h);
}

// Layer-5 agg fused with the final attention-concat epilogue (one node class).
// A1, AE1 are fp16 and already relu'd. P stays fp32 in registers.
// out row r: [0:64) A1*a0 | [64:128) AE1*a1 | [128:192) (P+A1)*a2
__global__ __launch_bounds__(256) void agg2_final_kernel(
    float* __restrict__ out,
    const uint4* __restrict__ A1, const uint4* __restrict__ AE1,
    const uint4* __restrict__ hw0, const uint4* __restrict__ hw1,
    const int* __restrict__ rp0, const int2* __restrict__ cv0,
    const int* __restrict__ rp1, const int2* __restrict__ cv1,
    const float* __restrict__ att, int N) {
    int gid = blockIdx.x * blockDim.x + threadIdx.x;
    if (gid >= N * 8) return;
    int r = gid >> 3, c = gid & 7;

    float acc0[8], acc1[8];
#pragma unroll
    for (int i = 0; i < 8; i++) { acc0[i] = 0.f; acc1[i] = 0.f; }
    agg_one(acc0, acc1, hw0, rp0, cv0, r, c);
    agg_one(acc0, acc1, hw1, rp1, cv1, r, c);

    float a0 = __ldg(att + 0), a1 = __ldg(att + 1), a2 = __ldg(att + 2);

    uint4 x1u = __ldg(A1 + (size_t)r * 8 + c);
    uint4 xeu = __ldg(AE1 + (size_t)r * 8 + c);
    const __half2* x1h = reinterpret_cast<const __half2*>(&x1u);
    const __half2* xeh = reinterpret_cast<const __half2*>(&xeu);

    float x1[8], xe[8];
#pragma unroll
    for (int i = 0; i < 4; i++) {
        float2 f1 = __half22float2(x1h[i]);
        float2 fe = __half22float2(xeh[i]);
        x1[2 * i] = f1.x; x1[2 * i + 1] = f1.y;
        xe[2 * i] = fe.x; xe[2 * i + 1] = fe.y;
    }

    float* o = out + (size_t)r * 192 + (size_t)c * 8;
#pragma unroll
    for (int i = 0; i < 2; i++) {
        float4 v0 = make_float4(x1[4 * i] * a0, x1[4 * i + 1] * a0,
                                x1[4 * i + 2] * a0, x1[4 * i + 3] * a0);
        float4 v1 = make_float4(xe[4 * i] * a1, xe[4 * i + 1] * a1,
                                xe[4 * i + 2] * a1, xe[4 * i + 3] * a1);
        float4 v2 = make_float4(
            (acc0[4 * i]     + acc1[4 * i]     + x1[4 * i])     * a2,
            (acc0[4 * i + 1] + acc1[4 * i + 1] + x1[4 * i + 1]) * a2,
            (acc0[4 * i + 2] + acc1[4 * i + 2] + x1[4 * i + 2]) * a2,
            (acc0[4 * i + 3] + acc1[4 * i + 3] + x1[4 * i + 3]) * a2);
        reinterpret_cast<float4*>(o + i * 4)[0]       = v0;
        reinterpret_cast<float4*>(o + 64 + i * 4)[0]  = v1;
        reinterpret_cast<float4*>(o + 128 + i * 4)[0] = v2;
    }
}

// ---------------------------------------------------------------------------
// Host launcher — proven R13 schedule: symmetric fork + CSR on SC + fused final
// ---------------------------------------------------------------------------
struct PipeCtx {
    cudaStream_t s1, sc;
    cudaEvent_t efork, eCSR;
    cudaEvent_t e0[5];
    cudaEvent_t e1[5];
    PipeCtx() {
        cudaStreamCreateWithFlags(&s1, cudaStreamNonBlocking);
        cudaStreamCreateWithFlags(&sc, cudaStreamNonBlocking);
        cudaEventCreateWithFlags(&efork, cudaEventDisableTiming);
        cudaEventCreateWithFlags(&eCSR,  cudaEventDisableTiming);
        for (int i = 0; i < 5; i++) {
            cudaEventCreateWithFlags(&e0[i], cudaEventDisableTiming);
            cudaEventCreateWithFlags(&e1[i], cudaEventDisableTiming);
        }
    }
};
static PipeCtx& pipe_ctx() { static PipeCtx c; return c; }

extern "C" void kernel_launch(void* const* d_in, const int* in_sizes, int n_in,
                              void* d_out, int out_size) {
    const float* feat0 = (const float*)d_in[0];
    const float* feat1 = (const float*)d_in[1];
    const int*   rows  = (const int*)  d_in[2];
    const int*   cols  = (const int*)  d_in[3];
    const float* vals  = (const float*)d_in[4];
    const float* Wl[5] = {(const float*)d_in[5], (const float*)d_in[6], (const float*)d_in[7],
                          (const float*)d_in[8], (const float*)d_in[9]};
    const float* att   = (const float*)d_in[10];
    float* out = (float*)d_out;

    const int N = in_sizes[0] / 128;   // 100000
    const int E = in_sizes[2] / 4;     // 1000000

    __half *A1, *AE1, *B, *C, *HW;
    int *cnt, *rowptr, *rowofs, *part;
    int2* cv;
    cudaGetSymbolAddress((void**)&A1,     g_A1);
    cudaGetSymbolAddress((void**)&AE1,    g_AE1);
    cudaGetSymbolAddress((void**)&B,      g_B);
    cudaGetSymbolAddress((void**)&C,      g_C);
    cudaGetSymbolAddress((void**)&HW,     g_HW);
    cudaGetSymbolAddress((void**)&cnt,    g_cnt);
    cudaGetSymbolAddress((void**)&rowptr, g_rowptr);
    cudaGetSymbolAddress((void**)&rowofs, g_rowofs);
    cudaGetSymbolAddress((void**)&cv,     g_cv);
    cudaGetSymbolAddress((void**)&part,   g_part);

    const int SMEM64  = (128 * (64 + 8)  + 64 * (64 + 8))  * 2;  // 27648 B
    const int SMEM128 = (128 * (128 + 8) + 64 * (128 + 8)) * 2;  // 52224 B
    cudaFuncSetAttribute(gemm_mma_kernel<128, false>,
                         cudaFuncAttributeMaxDynamicSharedMemorySize, SMEM128);
    cudaFuncSetAttribute(gemm_mma_kernel<64, true>,
                         cudaFuncAttributeMaxDynamicSharedMemorySize, SMEM64);

    PipeCtx& px = pipe_ctx();
    cudaStream_t S0 = 0, S1 = px.s1, SC = px.sc;

    const int gblocks = (N + 127) / 128;
    const int ablocks = (N * 8 + 255) / 256;
    const size_t half = (size_t)N * 64;

    auto rp  = [&](int t) { return rowptr + (size_t)t * (N + 1); };
    auto cvp = [&](int t) { return cv + (size_t)t * E; };
    auto hw  = [&](int t) { return HW + (size_t)t * half; };

    // ---- fork ----
    cudaEventRecord(px.efork, S0);
    cudaStreamWaitEvent(S1, px.efork, 0);
    cudaStreamWaitEvent(SC, px.efork, 0);

    // ---- CSR build on SC (overlaps layer-1 GEMMs) ----
    const int nb = (N + 255) / 256;
    cudaMemsetAsync(cnt, 0, (size_t)4 * N * sizeof(int), SC);
    {
        int blocks = (4 * E + 255) / 256;
        hist_kernel<<<blocks, 256, 0, SC>>>(cnt, rows, E, N);
        scan_phase1<<<dim3(nb, 4), 256, 0, SC>>>(cnt, part, N, nb);
        scan_phase2<<<1, 32, 0, SC>>>(part, rowptr, nb, N, E);
        scan_phase3<<<dim3(nb, 4), 256, 0, SC>>>(cnt, part, rowptr, rowofs, N, nb);
        fill_kernel<<<blocks, 256, 0, SC>>>(cv, rowofs, rows, cols, vals, E, N);
    }
    cudaEventRecord(px.eCSR, SC);

    auto gemm = [&](cudaStream_t s, int l, int t, const void* src, int din) {
        const float* Wt = Wl[l] + (size_t)t * din * 64;
        if (din == 128)
            gemm_mma_kernel<128, false><<<gblocks, 256, SMEM128, s>>>(hw(t), src, Wt, N);
        else
            gemm_mma_kernel<64, true><<<gblocks, 256, SMEM64, s>>>(hw(t), src, Wt, N);
    };

    __half* dsts[4] = {A1, AE1, B, C};
    for (int l = 0; l < 5; l++) {
        const void* p0;
        const void* p1;
        int din = (l == 0) ? 128 : 64;
        if (l == 0) { p0 = feat0; p1 = feat1; }
        else        { p0 = dsts[l - 1]; p1 = dsts[l - 1] + half; }

        // ----- S0 chain: G0(p0), [p1 ready] G1(p1), A01 -----
        gemm(S0, l, 0, p0, din);
        if (l > 0) cudaStreamWaitEvent(S0, px.e1[l - 1], 0);
        gemm(S0, l, 1, p1, din);
        if (l == 0) cudaStreamWaitEvent(S0, px.eCSR, 0);
        // ----- S1 chain: G3(p1), [p0 ready] G2(p0), A23 -----
        gemm(S1, l, 3, p1, din);
        if (l > 0) cudaStreamWaitEvent(S1, px.e0[l - 1], 0);
        gemm(S1, l, 2, p0, din);
        if (l == 0) cudaStreamWaitEvent(S1, px.eCSR, 0);

        if (l < 4) {
            __half* dst = dsts[l];
            agg2_relu_h_kernel<<<ablocks, 256, 0, S0>>>((uint4*)dst,
                (const uint4*)hw(0), (const uint4*)hw(1), rp(0), cvp(0), rp(1), cvp(1), N);
            cudaEventRecord(px.e0[l], S0);
            agg2_relu_h_kernel<<<ablocks, 256, 0, S1>>>((uint4*)(dst + half),
                (const uint4*)hw(2), (const uint4*)hw(3), rp(2), cvp(2), rp(3), cvp(3), N);
            cudaEventRecord(px.e1[l], S1);
        } else {
            agg2_final_kernel<<<ablocks, 256, 0, S0>>>(out,
                (const uint4*)A1, (const uint4*)AE1,
                (const uint4*)hw(0), (const uint4*)hw(1),
                rp(0), cvp(0), rp(1), cvp(1), att, N);
            cudaEventRecord(px.e0[l], S0);
            agg2_final_kernel<<<ablocks, 256, 0, S1>>>(out + (size_t)N * 192,
                (const uint4*)(A1 + half), (const uint4*)(AE1 + half),
                (const uint4*)hw(2), (const uint4*)hw(3),
                rp(2), cvp(2), rp(3), cvp(3), att, N);
            cudaEventRecord(px.e1[l], S1);
        }
    }

    // ---- join back to capture-origin stream ----
    cudaStreamWaitEvent(S0, px.e1[4], 0);
}